// round 5
// baseline (speedup 1.0000x reference)
#include <cuda_runtime.h>

// ---------------------------------------------------------------------------
// CMPNN, restructured:
//   x_proj = relu(x @ W_atom + b)                         [N,128]
//   h_bond_0[e] = relu(edge_attr[e] @ W_bond + b)          (implicit)
//   loop l=0..2:
//     msg[i] = sum_e m_e * max_e m_e   (edges with idx_i==i)
//     h_atom *= msg
//     U = h_atom @ W_l ; V = h_bondN @ W_l                [N,128] each
//     h_bondN[v] = relu(U[iI[v]] - V[iJ[v]] + b_l)   (only rows < N needed!)
//   final msg -> hfin = h_atom^2 * msg
//   out = [hfin | x_proj] @ W_lin + b_lin                 [N,64]
// h_bond [E,128] is never materialized: m_e = relu(U[i_e]-V[j_e]+b).
// ---------------------------------------------------------------------------

#define NN_MAX 30000
#define EE_MAX 480000

__device__ int g_is64;
__device__ int g_idxI[EE_MAX];
__device__ int g_idxJ[EE_MAX];
__device__ int g_deg[NN_MAX];
__device__ int g_rowptr[NN_MAX + 1];
__device__ int g_cursor[NN_MAX];
__device__ int g_sortedJ[EE_MAX];
__device__ int g_sortedE[EE_MAX];

__device__ __align__(16) float g_xproj[NN_MAX * 128];
__device__ __align__(16) float g_hatom[NN_MAX * 128];
__device__ __align__(16) float g_hbondN[NN_MAX * 128];
__device__ __align__(16) float g_U[NN_MAX * 128];
__device__ __align__(16) float g_V[NN_MAX * 128];

// ------------------------------- index setup -------------------------------

// Detect whether edge_index arrived as int64 (odd int32 words all zero) or int32.
__global__ void detect_kernel(const int* __restrict__ raw, int e) {
    __shared__ int nz;
    if (threadIdx.x == 0) nz = 0;
    __syncthreads();
    int K = e < 2048 ? e : 2048;
    for (int t = threadIdx.x; t < K; t += blockDim.x)
        if (raw[2 * t + 1] != 0) nz = 1;
    __syncthreads();
    if (threadIdx.x == 0) g_is64 = (nz == 0) ? 1 : 0;
}

__global__ void zero_deg_kernel(int n) {
    int t = blockIdx.x * blockDim.x + threadIdx.x;
    if (t < n) g_deg[t] = 0;
}

__global__ void convert_hist_kernel(const int* __restrict__ raw, int e) {
    int t = blockIdx.x * blockDim.x + threadIdx.x;
    if (t >= e) return;
    int i, j;
    if (g_is64) { i = raw[2 * t]; j = raw[2 * (e + t)]; }
    else        { i = raw[t];     j = raw[e + t]; }
    g_idxI[t] = i;
    g_idxJ[t] = j;
    atomicAdd(&g_deg[i], 1);
}

// Single-block exclusive scan over degrees -> row_ptr and cursor.
__global__ void scan_kernel(int n) {
    __shared__ int sh[1024];
    __shared__ int s_carry;
    if (threadIdx.x == 0) s_carry = 0;
    __syncthreads();
    for (int base = 0; base < n; base += 1024) {
        int i = base + (int)threadIdx.x;
        int v = (i < n) ? g_deg[i] : 0;
        sh[threadIdx.x] = v;
        __syncthreads();
        for (int off = 1; off < 1024; off <<= 1) {
            int t = 0;
            if ((int)threadIdx.x >= off) t = sh[threadIdx.x - off];
            __syncthreads();
            sh[threadIdx.x] += t;
            __syncthreads();
        }
        int incl = sh[threadIdx.x];
        int carry_local = s_carry;
        if (i < n) {
            int excl = carry_local + incl - v;
            g_rowptr[i] = excl;
            g_cursor[i] = excl;
        }
        __syncthreads();
        if (threadIdx.x == 1023) s_carry = carry_local + sh[1023];
        __syncthreads();
    }
    if (threadIdx.x == 0) g_rowptr[n] = s_carry;
}

__global__ void scatter_kernel(int e) {
    int t = blockIdx.x * blockDim.x + threadIdx.x;
    if (t >= e) return;
    int i = g_idxI[t];
    int p = atomicAdd(&g_cursor[i], 1);
    g_sortedJ[p] = g_idxJ[t];
    g_sortedE[p] = t;
}

// ------------------------------ 128-wide SGEMM ------------------------------
// C[M,128] = act(A[M,128] @ W[128,128] + bias). Dual-source: blocks < nblk use
// (A1,C1), the rest (A2,C2). BM=128, BN=128, BK=32, 256 threads, 8x8 per thread.

__global__ __launch_bounds__(256) void gemm128_kernel(
    const float* __restrict__ A1, const float* __restrict__ A2,
    const float* __restrict__ W, const float* __restrict__ bias,
    float* __restrict__ C1, float* __restrict__ C2,
    int M, int nblk, int act)
{
    __shared__ float As[32][132];
    __shared__ float Ws[32][128];
    const float* __restrict__ A;
    float* __restrict__ C;
    int bx = blockIdx.x;
    if (bx < nblk) { A = A1; C = C1; }
    else           { A = A2; C = C2; bx -= nblk; }
    int row0 = bx * 128;
    int tid = threadIdx.x;
    int tx = tid & 15, ty = tid >> 4;
    float acc[8][8];
#pragma unroll
    for (int i = 0; i < 8; i++)
#pragma unroll
        for (int j = 0; j < 8; j++) acc[i][j] = 0.f;

    for (int k0 = 0; k0 < 128; k0 += 32) {
#pragma unroll
        for (int i = 0; i < 4; i++) {
            int idx = tid + i * 256;         // 0..1023
            int m = idx >> 3;                // row within tile
            int c4 = (idx & 7) * 4;          // col within k-chunk
            float4 v = make_float4(0.f, 0.f, 0.f, 0.f);
            int r = row0 + m;
            if (r < M) v = *(const float4*)(A + (size_t)r * 128 + k0 + c4);
            As[c4 + 0][m] = v.x;
            As[c4 + 1][m] = v.y;
            As[c4 + 2][m] = v.z;
            As[c4 + 3][m] = v.w;
        }
#pragma unroll
        for (int i = 0; i < 4; i++) {
            int idx = tid + i * 256;
            int k = idx >> 5;
            int n4 = (idx & 31) * 4;
            *(float4*)(&Ws[k][n4]) = *(const float4*)(W + (size_t)(k0 + k) * 128 + n4);
        }
        __syncthreads();
#pragma unroll
        for (int k = 0; k < 32; k++) {
            float a[8], b[8];
            *(float4*)(&a[0]) = *(const float4*)(&As[k][ty * 8]);
            *(float4*)(&a[4]) = *(const float4*)(&As[k][ty * 8 + 4]);
            *(float4*)(&b[0]) = *(const float4*)(&Ws[k][tx * 8]);
            *(float4*)(&b[4]) = *(const float4*)(&Ws[k][tx * 8 + 4]);
#pragma unroll
            for (int i = 0; i < 8; i++)
#pragma unroll
                for (int j = 0; j < 8; j++)
                    acc[i][j] = fmaf(a[i], b[j], acc[i][j]);
        }
        __syncthreads();
    }
#pragma unroll
    for (int i = 0; i < 8; i++) {
        int r = row0 + ty * 8 + i;
        if (r < M) {
            float vals[8];
#pragma unroll
            for (int j = 0; j < 8; j++) {
                float v = acc[i][j];
                if (bias) v += bias[tx * 8 + j];
                if (act) v = fmaxf(v, 0.f);
                vals[j] = v;
            }
            float* op = C + (size_t)r * 128 + tx * 8;
            *(float4*)(op)     = *(float4*)(&vals[0]);
            *(float4*)(op + 4) = *(float4*)(&vals[4]);
        }
    }
}

// ------------------------- per-edge helpers / agg ---------------------------

__device__ __forceinline__ void agg_step(const float4& u, const float4& b,
                                         const float4& v, float4& s, float4& mx) {
    float m0 = fmaxf(u.x - v.x + b.x, 0.f);
    float m1 = fmaxf(u.y - v.y + b.y, 0.f);
    float m2 = fmaxf(u.z - v.z + b.z, 0.f);
    float m3 = fmaxf(u.w - v.w + b.w, 0.f);
    s.x += m0; s.y += m1; s.z += m2; s.w += m3;
    mx.x = fmaxf(mx.x, m0); mx.y = fmaxf(mx.y, m1);
    mx.z = fmaxf(mx.z, m2); mx.w = fmaxf(mx.w, m3);
}

// Layers 1..3 aggregation. Warp per node. m_e = relu(U[i]-V[j_e]+b).
// final_mode==0: h_atom *= sum*max.  final_mode==1: hfin(=g_hbondN) = h_atom^2*sum*max.
__global__ __launch_bounds__(256) void agg_kernel(
    const float* __restrict__ U, const float* __restrict__ V,
    const float* __restrict__ bias, int n, int final_mode)
{
    int gw = (blockIdx.x * blockDim.x + threadIdx.x) >> 5;
    int lane = threadIdx.x & 31;
    if (gw >= n) return;
    int start = g_rowptr[gw], end = g_rowptr[gw + 1];
    float4 u = *(const float4*)(U + (size_t)gw * 128 + lane * 4);
    float4 b = *(const float4*)(bias + lane * 4);
    float4 s  = make_float4(0.f, 0.f, 0.f, 0.f);
    float4 mx = make_float4(0.f, 0.f, 0.f, 0.f);
    for (int c = start; c < end; c += 32) {
        int cnt = end - c; if (cnt > 32) cnt = 32;
        int myj = g_sortedJ[c + (lane < cnt ? lane : 0)];
        int t = 0;
        for (; t + 4 <= cnt; t += 4) {
            int j0 = __shfl_sync(0xffffffffu, myj, t);
            int j1 = __shfl_sync(0xffffffffu, myj, t + 1);
            int j2 = __shfl_sync(0xffffffffu, myj, t + 2);
            int j3 = __shfl_sync(0xffffffffu, myj, t + 3);
            float4 v0 = *(const float4*)(V + (size_t)j0 * 128 + lane * 4);
            float4 v1 = *(const float4*)(V + (size_t)j1 * 128 + lane * 4);
            float4 v2 = *(const float4*)(V + (size_t)j2 * 128 + lane * 4);
            float4 v3 = *(const float4*)(V + (size_t)j3 * 128 + lane * 4);
            agg_step(u, b, v0, s, mx);
            agg_step(u, b, v1, s, mx);
            agg_step(u, b, v2, s, mx);
            agg_step(u, b, v3, s, mx);
        }
        for (; t < cnt; t++) {
            int j0 = __shfl_sync(0xffffffffu, myj, t);
            float4 v0 = *(const float4*)(V + (size_t)j0 * 128 + lane * 4);
            agg_step(u, b, v0, s, mx);
        }
    }
    float4 msg = make_float4(s.x * mx.x, s.y * mx.y, s.z * mx.z, s.w * mx.w);
    float* hp = g_hatom + (size_t)gw * 128 + lane * 4;
    float4 h = *(float4*)hp;
    if (!final_mode) {
        h.x *= msg.x; h.y *= msg.y; h.z *= msg.z; h.w *= msg.w;
        *(float4*)hp = h;
    } else {
        float4 o = make_float4(h.x * h.x * msg.x, h.y * h.y * msg.y,
                               h.z * h.z * msg.z, h.w * h.w * msg.w);
        *(float4*)(g_hbondN + (size_t)gw * 128 + lane * 4) = o;
    }
}

// Layer-0 aggregation: m_e = relu(edge_attr[e] @ W_bond + b_bond), fused matvec.
// Epilogue: h_atom = x_proj * (sum*max).
__global__ __launch_bounds__(256) void agg0_kernel(
    const float* __restrict__ eattr, const float* __restrict__ Wb,
    const float* __restrict__ bb, int n)
{
    __shared__ float Wbs[16][128];
    for (int i = threadIdx.x; i < 512; i += 256)
        ((float4*)Wbs)[i] = ((const float4*)Wb)[i];
    __syncthreads();
    int gw = (blockIdx.x * blockDim.x + threadIdx.x) >> 5;
    int lane = threadIdx.x & 31;
    if (gw >= n) return;
    int start = g_rowptr[gw], end = g_rowptr[gw + 1];
    float4 b = *(const float4*)(bb + lane * 4);
    float4 s  = make_float4(0.f, 0.f, 0.f, 0.f);
    float4 mx = make_float4(0.f, 0.f, 0.f, 0.f);
    for (int c = start; c < end; c += 32) {
        int cnt = end - c; if (cnt > 32) cnt = 32;
        int myE = g_sortedE[c + (lane < cnt ? lane : 0)];
        for (int t = 0; t < cnt; t++) {
            int eid = __shfl_sync(0xffffffffu, myE, t);
            const float4* ea = (const float4*)(eattr + (size_t)eid * 16);
            float ec[16];
            *(float4*)(&ec[0])  = ea[0];
            *(float4*)(&ec[4])  = ea[1];
            *(float4*)(&ec[8])  = ea[2];
            *(float4*)(&ec[12]) = ea[3];
            float4 m = b;
#pragma unroll
            for (int q = 0; q < 16; q++) {
                float4 w = *(const float4*)(&Wbs[q][lane * 4]);
                m.x = fmaf(ec[q], w.x, m.x);
                m.y = fmaf(ec[q], w.y, m.y);
                m.z = fmaf(ec[q], w.z, m.z);
                m.w = fmaf(ec[q], w.w, m.w);
            }
            m.x = fmaxf(m.x, 0.f); m.y = fmaxf(m.y, 0.f);
            m.z = fmaxf(m.z, 0.f); m.w = fmaxf(m.w, 0.f);
            s.x += m.x; s.y += m.y; s.z += m.z; s.w += m.w;
            mx.x = fmaxf(mx.x, m.x); mx.y = fmaxf(mx.y, m.y);
            mx.z = fmaxf(mx.z, m.z); mx.w = fmaxf(mx.w, m.w);
        }
    }
    float4 xp = *(const float4*)(g_xproj + (size_t)gw * 128 + lane * 4);
    float4 o = make_float4(xp.x * s.x * mx.x, xp.y * s.y * mx.y,
                           xp.z * s.z * mx.z, xp.w * s.w * mx.w);
    *(float4*)(g_hatom + (size_t)gw * 128 + lane * 4) = o;
}

// h_bondN_0[v] = relu(edge_attr[v] @ W_bond + b_bond), v < N. Warp per row.
__global__ __launch_bounds__(256) void bond0_kernel(
    const float* __restrict__ eattr, const float* __restrict__ Wb,
    const float* __restrict__ bb, int n)
{
    __shared__ float Wbs[16][128];
    for (int i = threadIdx.x; i < 512; i += 256)
        ((float4*)Wbs)[i] = ((const float4*)Wb)[i];
    __syncthreads();
    int v = (blockIdx.x * blockDim.x + threadIdx.x) >> 5;
    int lane = threadIdx.x & 31;
    if (v >= n) return;
    float4 m = *(const float4*)(bb + lane * 4);
    const float4* ea = (const float4*)(eattr + (size_t)v * 16);
    float ec[16];
    *(float4*)(&ec[0])  = ea[0];
    *(float4*)(&ec[4])  = ea[1];
    *(float4*)(&ec[8])  = ea[2];
    *(float4*)(&ec[12]) = ea[3];
#pragma unroll
    for (int q = 0; q < 16; q++) {
        float4 w = *(const float4*)(&Wbs[q][lane * 4]);
        m.x = fmaf(ec[q], w.x, m.x);
        m.y = fmaf(ec[q], w.y, m.y);
        m.z = fmaf(ec[q], w.z, m.z);
        m.w = fmaf(ec[q], w.w, m.w);
    }
    m.x = fmaxf(m.x, 0.f); m.y = fmaxf(m.y, 0.f);
    m.z = fmaxf(m.z, 0.f); m.w = fmaxf(m.w, 0.f);
    *(float4*)(g_hbondN + (size_t)v * 128 + lane * 4) = m;
}

// h_bondN[v] = relu(U[idxI[v]] - V[idxJ[v]] + b), v < N (edge ids 0..N-1).
__global__ __launch_bounds__(256) void bond_update_kernel(
    const float* __restrict__ bias, int n)
{
    int v = (blockIdx.x * blockDim.x + threadIdx.x) >> 5;
    int lane = threadIdx.x & 31;
    if (v >= n) return;
    int i = g_idxI[v], j = g_idxJ[v];
    float4 u  = *(const float4*)(g_U + (size_t)i * 128 + lane * 4);
    float4 vv = *(const float4*)(g_V + (size_t)j * 128 + lane * 4);
    float4 b  = *(const float4*)(bias + lane * 4);
    float4 o = make_float4(fmaxf(u.x - vv.x + b.x, 0.f),
                           fmaxf(u.y - vv.y + b.y, 0.f),
                           fmaxf(u.z - vv.z + b.z, 0.f),
                           fmaxf(u.w - vv.w + b.w, 0.f));
    *(float4*)(g_hbondN + (size_t)v * 128 + lane * 4) = o;
}

// out[N,64] = [hfin | x_proj] @ W_lin[256,64] + b_lin. BM=128, BK=32.
__global__ __launch_bounds__(256) void gemm_out_kernel(
    const float* __restrict__ Wlin, const float* __restrict__ blin,
    float* __restrict__ out, int n)
{
    __shared__ float As[32][132];
    __shared__ float Ws[32][64];
    int tid = threadIdx.x;
    int row0 = blockIdx.x * 128;
    int tx = tid & 7;    // 8 col groups x 8 cols
    int ty = tid >> 3;   // 32 row groups x 4 rows
    float acc[4][8];
#pragma unroll
    for (int i = 0; i < 4; i++)
#pragma unroll
        for (int j = 0; j < 8; j++) acc[i][j] = 0.f;

    for (int k0 = 0; k0 < 256; k0 += 32) {
        const float* Asrc = (k0 < 128) ? g_hbondN : g_xproj;  // hfin lives in g_hbondN
        int kb = k0 & 127;
#pragma unroll
        for (int i = 0; i < 4; i++) {
            int idx = tid + i * 256;
            int m = idx >> 3;
            int c4 = (idx & 7) * 4;
            float4 v = make_float4(0.f, 0.f, 0.f, 0.f);
            int r = row0 + m;
            if (r < n) v = *(const float4*)(Asrc + (size_t)r * 128 + kb + c4);
            As[c4 + 0][m] = v.x;
            As[c4 + 1][m] = v.y;
            As[c4 + 2][m] = v.z;
            As[c4 + 3][m] = v.w;
        }
#pragma unroll
        for (int i = 0; i < 2; i++) {
            int idx = tid + i * 256;      // 0..511
            int k = idx >> 4;
            int n4 = (idx & 15) * 4;
            *(float4*)(&Ws[k][n4]) = *(const float4*)(Wlin + (size_t)(k0 + k) * 64 + n4);
        }
        __syncthreads();
#pragma unroll
        for (int k = 0; k < 32; k++) {
            float a[4], b[8];
            *(float4*)(&a[0]) = *(const float4*)(&As[k][ty * 4]);
            *(float4*)(&b[0]) = *(const float4*)(&Ws[k][tx * 8]);
            *(float4*)(&b[4]) = *(const float4*)(&Ws[k][tx * 8 + 4]);
#pragma unroll
            for (int i = 0; i < 4; i++)
#pragma unroll
                for (int j = 0; j < 8; j++)
                    acc[i][j] = fmaf(a[i], b[j], acc[i][j]);
        }
        __syncthreads();
    }
#pragma unroll
    for (int i = 0; i < 4; i++) {
        int r = row0 + ty * 4 + i;
        if (r < n) {
            float vals[8];
#pragma unroll
            for (int j = 0; j < 8; j++) vals[j] = acc[i][j] + blin[tx * 8 + j];
            float* op = out + (size_t)r * 64 + tx * 8;
            *(float4*)(op)     = *(float4*)(&vals[0]);
            *(float4*)(op + 4) = *(float4*)(&vals[4]);
        }
    }
}

// --------------------------------- launch -----------------------------------

extern "C" void kernel_launch(void* const* d_in, const int* in_sizes, int n_in,
                              void* d_out, int out_size) {
    const float* x      = (const float*)d_in[0];
    const int*   eraw   = (const int*)d_in[1];
    const float* eattr  = (const float*)d_in[2];
    const float* W_atom = (const float*)d_in[3];
    const float* b_atom = (const float*)d_in[4];
    const float* W_bond = (const float*)d_in[5];
    const float* b_bond = (const float*)d_in[6];
    const float* W_seq  = (const float*)d_in[7];
    const float* b_seq  = (const float*)d_in[8];
    const float* W_lin  = (const float*)d_in[9];
    const float* b_lin  = (const float*)d_in[10];
    float* out = (float*)d_out;

    int n = in_sizes[0] / 128;   // 30000
    int e = in_sizes[2] / 16;    // 480000
    if (n > NN_MAX) n = NN_MAX;
    if (e > EE_MAX) e = EE_MAX;

    float *p_xproj, *p_hatom, *p_hbondN, *p_U, *p_V;
    cudaGetSymbolAddress((void**)&p_xproj,  g_xproj);
    cudaGetSymbolAddress((void**)&p_hatom,  g_hatom);
    cudaGetSymbolAddress((void**)&p_hbondN, g_hbondN);
    cudaGetSymbolAddress((void**)&p_U,      g_U);
    cudaGetSymbolAddress((void**)&p_V,      g_V);

    int eb  = (e + 255) / 256;
    int nb  = (n + 255) / 256;
    int nwb = (n * 32 + 255) / 256;     // warp-per-node grids
    int gblk = (n + 127) / 128;         // GEMM row blocks

    // CSR build
    detect_kernel<<<1, 256>>>(eraw, e);
    zero_deg_kernel<<<nb, 256>>>(n);
    convert_hist_kernel<<<eb, 256>>>(eraw, e);
    scan_kernel<<<1, 1024>>>(n);
    scatter_kernel<<<eb, 256>>>(e);

    // x_proj = relu(x @ W_atom + b_atom)
    gemm128_kernel<<<gblk, 256>>>(x, x, W_atom, b_atom, p_xproj, p_xproj, n, gblk, 1);
    // h_bondN_0 = relu(edge_attr[0:n] @ W_bond + b_bond)
    bond0_kernel<<<nwb, 256>>>(eattr, W_bond, b_bond, n);
    // msg_0 (fused matvec over edges) and h_atom_1 = x_proj * msg_0
    agg0_kernel<<<nwb, 256>>>(eattr, W_bond, b_bond, n);

    for (int l = 0; l < 3; l++) {
        const float* Wl = W_seq + (size_t)l * 128 * 128;
        const float* bl = b_seq + (size_t)l * 128;
        // U = h_atom @ W_l ; V = h_bondN @ W_l   (one dual-source launch)
        gemm128_kernel<<<2 * gblk, 256>>>(p_hatom, p_hbondN, Wl, (const float*)0,
                                          p_U, p_V, n, gblk, 0);
        // h_bondN_{l+1}[v] = relu(U[i_v] - V[j_v] + b_l)   (not needed after l=1)
        if (l < 2) bond_update_kernel<<<nwb, 256>>>(bl, n);
        // msg_{l+1}: l<2 -> h_atom *= msg ; l==2 -> hfin = h_atom^2 * msg (into g_hbondN)
        agg_kernel<<<nwb, 256>>>(p_U, p_V, bl, n, (l == 2) ? 1 : 0);
    }

    // out = [hfin | x_proj] @ W_lin + b_lin
    gemm_out_kernel<<<gblk, 256>>>(W_lin, b_lin, out, n);
}